// round 9
// baseline (speedup 1.0000x reference)
#include <cuda_runtime.h>
#include <cstdint>

// ---------------- problem shape ----------------
#define TOK   32768
#define HDIM  4096
#define NE    64
#define BM    128            // tokens per CTA
#define BK    32             // k per chunk
#define NCH   128            // HDIM / BK
#define NT    256            // threads (8 warps)
#define TAU   1e-4f

// smem: dynamic 64KB
//  x[k][t]  : k*512 + t*4          (16KB per buffer)
//  w[k][q][eg][4] dup'd: k*512 + q*128 + eg*16   (16KB per buffer)
#define XB0   0
#define XB1   16384
#define WB0   32768
#define WB1   49152
#define SMEMB 65536

// ---------------- device globals ----------------
// g_wd: [chunk 128][k 32][q 4][eg 8][4 floats]; float c of (q,eg) is
// W[eg*8 + 2q + (c>>1)][chunk*32+k]  (duplicated pairs for direct f32x2 use)
__device__ float g_wd[NCH * BK * 128];
__device__ int g_flag_count;
__device__ int g_flag_list[TOK];

// ---------------- packed fp32x2 FMA (opaque) ----------------
#define FMA2(d, a, b) \
    asm("fma.rn.f32x2 %0, %1, %2, %0;" : "+l"(d) : "l"(a), "l"(b))
#define UNPK2(lo, hi, p) \
    asm("mov.b64 {%0, %1}, %2;" : "=f"(lo), "=f"(hi) : "l"(p))

__device__ __forceinline__ uint32_t s2u(const void* p) {
    uint32_t a;
    asm("{ .reg .u64 t; cvta.to.shared.u64 t, %1; cvt.u32.u64 %0, t; }" : "=r"(a) : "l"(p));
    return a;
}
__device__ __forceinline__ void cpasync16(uint32_t dst, const void* src) {
    asm volatile("cp.async.ca.shared.global [%0], [%1], 16;" :: "r"(dst), "l"(src));
}
#define CP_COMMIT() asm volatile("cp.async.commit_group;" ::: "memory")
#define CP_WAIT0()  asm volatile("cp.async.wait_group 0;" ::: "memory")

// ---------------- prep: build transposed + duplicated W table ----------------
__global__ void prep_wd(const float* __restrict__ W) {
    int id = blockIdx.x * 256 + threadIdx.x;        // 524288 threads
    if (id == 0) g_flag_count = 0;
    if (id >= NCH * BK * 128) return;
    int c  = id >> 12;          // chunk
    int r  = id & 4095;
    int k  = r >> 7;            // k within chunk
    int f  = r & 127;           // float within 512B row
    int q  = f >> 5;
    int eg = (f >> 2) & 7;
    int cc = f & 3;
    int e  = eg * 8 + 2 * q + (cc >> 1);
    g_wd[id] = W[(size_t)e * HDIM + c * BK + k];
}

// ---------------- main: fp32 FFMA2 GEMM + fused softmax/top2 ----------------
__global__ void __launch_bounds__(NT, 2)
moe_gate_ffma(const float* __restrict__ X, float* __restrict__ out) {
    extern __shared__ __align__(16) char smc[];
    const uint32_t sbase = s2u(smc);

    const int tid  = threadIdx.x;
    const int lane = tid & 31, wid = tid >> 5;      // 8 warps
    const int eg   = lane & 7;                      // expert group (8 experts)
    const int tg   = (lane >> 3) & 3;               // token group (4 tokens)
    const int t0   = wid * 16 + tg * 4;             // first token of this thread
    const int tok0 = blockIdx.x * BM;

    // x loader role: token lt, half lh (16 floats per thread per chunk)
    const int lt = tid & 127, lh = tid >> 7;
    const float4* Xrow = (const float4*)(X + (size_t)(tok0 + lt) * HDIM + lh * 16);

    const uint32_t xoff = (uint32_t)(t0 * 4);       // byte offset of x pair quad
    const uint32_t woff = (uint32_t)(eg * 16);      // byte offset of w quad

    // acc[ei][tp]: expert e = eg*8 + ei, token pair (t0+2tp, t0+2tp+1)
    uint64_t acc[8][2];
#pragma unroll
    for (int i = 0; i < 8; ++i) { acc[i][0] = 0ull; acc[i][1] = 0ull; }

    float4 xa[4];

#define LDG_X(cc_)                                                        \
    {                                                                     \
        _Pragma("unroll")                                                 \
        for (int it = 0; it < 4; ++it) xa[it] = Xrow[(cc_) * 8 + it];     \
    }

#define STS_X(xb)                                                         \
    {                                                                     \
        _Pragma("unroll")                                                 \
        for (int it = 0; it < 4; ++it) {                                  \
            int k0 = lh * 16 + it * 4;                                    \
            float* d = (float*)(smc + (xb) + lt * 4);                     \
            d[(k0 + 0) * 128] = xa[it].x;                                 \
            d[(k0 + 1) * 128] = xa[it].y;                                 \
            d[(k0 + 2) * 128] = xa[it].z;                                 \
            d[(k0 + 3) * 128] = xa[it].w;                                 \
        }                                                                 \
    }

#define CP_W(cc_, wb)                                                     \
    {                                                                     \
        const char* ws = (const char*)g_wd + (size_t)(cc_) * 16384;       \
        _Pragma("unroll")                                                 \
        for (int q = 0; q < 4; ++q) {                                     \
            int idx = q * NT + tid;                                       \
            cpasync16(sbase + (wb) + idx * 16, ws + idx * 16);            \
        }                                                                 \
        CP_COMMIT();                                                      \
    }

    // ---- stage chunk 0 ----
    LDG_X(0);
    CP_W(0, WB0);
    STS_X(XB0);
    CP_WAIT0();
    __syncthreads();

    for (int c = 0; c < NCH; ++c) {
        const int xcur = (c & 1) ? XB1 : XB0;
        const int wcur = (c & 1) ? WB1 : WB0;
        const int xnxt = (c & 1) ? XB0 : XB1;
        const int wnxt = (c & 1) ? WB0 : WB1;
        const bool more = (c + 1 < NCH);

        if (more) {
            LDG_X(c + 1);
            CP_W(c + 1, wnxt);
        }

        const char* xb = smc + xcur;
        const char* wb = smc + wcur;
#pragma unroll 8
        for (int kk = 0; kk < BK; ++kk) {
            ulonglong2 xp = *(const ulonglong2*)(xb + kk * 512 + xoff);
            ulonglong2 w0 = *(const ulonglong2*)(wb + kk * 512 + 0   + woff);
            ulonglong2 w1 = *(const ulonglong2*)(wb + kk * 512 + 128 + woff);
            ulonglong2 w2 = *(const ulonglong2*)(wb + kk * 512 + 256 + woff);
            ulonglong2 w3 = *(const ulonglong2*)(wb + kk * 512 + 384 + woff);
            FMA2(acc[0][0], xp.x, w0.x);  FMA2(acc[0][1], xp.y, w0.x);
            FMA2(acc[1][0], xp.x, w0.y);  FMA2(acc[1][1], xp.y, w0.y);
            FMA2(acc[2][0], xp.x, w1.x);  FMA2(acc[2][1], xp.y, w1.x);
            FMA2(acc[3][0], xp.x, w1.y);  FMA2(acc[3][1], xp.y, w1.y);
            FMA2(acc[4][0], xp.x, w2.x);  FMA2(acc[4][1], xp.y, w2.x);
            FMA2(acc[5][0], xp.x, w2.y);  FMA2(acc[5][1], xp.y, w2.y);
            FMA2(acc[6][0], xp.x, w3.x);  FMA2(acc[6][1], xp.y, w3.x);
            FMA2(acc[7][0], xp.x, w3.y);  FMA2(acc[7][1], xp.y, w3.y);
        }

        if (more) {
            STS_X(xnxt);
            CP_WAIT0();
        }
        __syncthreads();
    }

    // ---- scatter logits into smem overlay lg[128][66] ----
    float* lg = (float*)smc;
#pragma unroll
    for (int ei = 0; ei < 8; ++ei) {
        int e = eg * 8 + ei;
#pragma unroll
        for (int tp = 0; tp < 2; ++tp) {
            float lo, hi;
            UNPK2(lo, hi, acc[ei][tp]);
            int t = t0 + 2 * tp;
            lg[t * 66 + e]       = lo;
            lg[(t + 1) * 66 + e] = hi;
        }
    }
    __syncthreads();

    // ---- per-token softmax + top-3 + near-tie flag (threads 0..127) ----
    if (tid < BM) {
        const int t = tid;
        const float* row = lg + t * 66;
        float mx = row[0];
#pragma unroll 8
        for (int e = 1; e < NE; ++e) mx = fmaxf(mx, row[e]);
        float sum = 0.0f;
        float s1 = -3.4e38f, s2 = -3.4e38f, s3 = -3.4e38f;
        int i1 = 0, i2 = 0;
#pragma unroll 8
        for (int e = 0; e < NE; ++e) {
            float l = row[e];
            sum += expf(l - mx);
            if (l > s1)      { s3 = s2; s2 = s1; i2 = i1; s1 = l; i1 = e; }
            else if (l > s2) { s3 = s2; s2 = l; i2 = e; }
            else if (l > s3) { s3 = l; }
        }
        float inv = 1.0f / sum;
        int gt = tok0 + t;
        out[2 * gt]               = (float)i1;
        out[2 * gt + 1]           = (float)i2;
        out[2 * TOK + 2 * gt]     = expf(s1 - mx) * inv;
        out[2 * TOK + 2 * gt + 1] = expf(s2 - mx) * inv;
        if ((s1 - s2 < TAU) || (s2 - s3 < TAU)) {
            int sl = atomicAdd(&g_flag_count, 1);
            if (sl < TOK) g_flag_list[sl] = gt;
        }
    }
}

// ---------------- cleanup: fp64 recompute of near-tie tokens (8-way ILP) ----------------
__global__ void cleanup_kernel(const float* __restrict__ X, const float* __restrict__ W,
                               float* __restrict__ out) {
    __shared__ double sred[128];
    __shared__ double lgs[64];
    int nf = g_flag_count;
    if (nf > TOK) nf = TOK;
    for (int i = blockIdx.x; i < nf; i += gridDim.x) {
        int t = g_flag_list[i];
        int e  = threadIdx.x & 63;
        int kh = threadIdx.x >> 6;
        const float4* xr = (const float4*)(X + (size_t)t * HDIM + kh * 2048);
        const float4* wr = (const float4*)(W + (size_t)e * HDIM + kh * 2048);
        double a0 = 0, a1 = 0, a2 = 0, a3 = 0, a4 = 0, a5 = 0, a6 = 0, a7 = 0;
#pragma unroll 4
        for (int q = 0; q < 512; q += 2) {
            float4 x0 = xr[q],     w0 = wr[q];
            float4 x1 = xr[q + 1], w1 = wr[q + 1];
            a0 += (double)x0.x * w0.x;  a1 += (double)x0.y * w0.y;
            a2 += (double)x0.z * w0.z;  a3 += (double)x0.w * w0.w;
            a4 += (double)x1.x * w1.x;  a5 += (double)x1.y * w1.y;
            a6 += (double)x1.z * w1.z;  a7 += (double)x1.w * w1.w;
        }
        sred[threadIdx.x] = ((a0 + a1) + (a2 + a3)) + ((a4 + a5) + (a6 + a7));
        __syncthreads();
        if (threadIdx.x < 64) lgs[threadIdx.x] = sred[threadIdx.x] + sred[threadIdx.x + 64];
        __syncthreads();
        if (threadIdx.x == 0) {
            double mx = lgs[0];
            for (int q = 1; q < NE; ++q) if (lgs[q] > mx) mx = lgs[q];
            double sum = 0.0;
            double s1 = -1e300, s2 = -1e300;
            int i1 = 0, i2 = 0;
            for (int q = 0; q < NE; ++q) {
                double l = lgs[q];
                sum += exp(l - mx);
                if (l > s1)      { s2 = s1; i2 = i1; s1 = l; i1 = q; }
                else if (l > s2) { s2 = l; i2 = q; }
            }
            double inv = 1.0 / sum;
            out[2 * t]               = (float)i1;
            out[2 * t + 1]           = (float)i2;
            out[2 * TOK + 2 * t]     = (float)(exp(s1 - mx) * inv);
            out[2 * TOK + 2 * t + 1] = (float)(exp(s2 - mx) * inv);
        }
        __syncthreads();
    }
}

// ---------------- launch ----------------
extern "C" void kernel_launch(void* const* d_in, const int* in_sizes, int n_in,
                              void* d_out, int out_size) {
    const float* X = (const float*)d_in[0];
    const float* W = (const float*)d_in[1];
    float* out = (float*)d_out;

    static bool once = []() {
        cudaFuncSetAttribute(moe_gate_ffma, cudaFuncAttributeMaxDynamicSharedMemorySize,
                             SMEMB);
        return true;
    }();
    (void)once;

    prep_wd<<<2048, 256>>>(W);
    moe_gate_ffma<<<TOK / BM, NT, SMEMB>>>(X, out);
    cleanup_kernel<<<256, 128>>>(X, W, out);
}

// round 10
// speedup vs baseline: 1.6106x; 1.6106x over previous
#include <cuda_runtime.h>
#include <cuda_bf16.h>
#include <cstdint>

// ---------------- problem shape ----------------
#define TOK   32768
#define HDIM  4096
#define NE    64
#define BM    128            // tokens per CTA
#define KI    64             // k per iteration
#define KT    48             // tensor k per iteration (3 ksteps of 16)
#define KF    16             // fma k per iteration
#define NIT   64             // HDIM / KI
#define NT    256            // threads (8 warps)
#define TAU   1e-4f

// smem per buffer (pad-112B tensor rows, pad-80B fma X rows):
#define XH_OFF 0                 // 128 tok x 112B            = 14336
#define XL_OFF 14336             // 128 tok x 112B            = 14336
#define W3_OFF 28672             // 2 planes x 64 e x 112B    = 14336
#define XF_OFF 43008             // 128 tok x 80B (64B data)  = 10240
#define WF_OFF 53248             // 16 k x 256B               =  4096
#define BUFB   57344
#define SMEMB  (2 * BUFB)        // 114688 per CTA -> 2 CTAs/SM

// ---------------- device globals ----------------
__device__ unsigned char g_w3[NIT * 14336];   // [iter][plane h/l][e 64][112B rows]
__device__ float g_wf[NIT * 16 * 64];         // [iter][k 16][e 64] fp32
__device__ int g_flag_count;
__device__ int g_flag_list[TOK];

// ---------------- helpers ----------------
__device__ __forceinline__ uint32_t s2u(const void* p) {
    uint32_t a;
    asm("{ .reg .u64 t; cvta.to.shared.u64 t, %1; cvt.u32.u64 %0, t; }" : "=r"(a) : "l"(p));
    return a;
}
__device__ __forceinline__ uint32_t cvt2bf(float f1, float f0) {
    uint32_t d;
    asm("cvt.rn.bf16x2.f32 %0, %1, %2;" : "=r"(d) : "f"(f1), "f"(f0));
    return d;
}
__device__ __forceinline__ void splitpair(float f0, float f1, uint32_t& h, uint32_t& l) {
    h = cvt2bf(f1, f0);
    float h0 = __uint_as_float(h << 16);
    float h1 = __uint_as_float(h & 0xFFFF0000u);
    l = cvt2bf(f1 - h1, f0 - h0);
}
__device__ __forceinline__ void ldsm4(uint32_t* r, uint32_t addr) {
    asm volatile("ldmatrix.sync.aligned.m8n8.x4.shared.b16 {%0,%1,%2,%3}, [%4];"
                 : "=r"(r[0]), "=r"(r[1]), "=r"(r[2]), "=r"(r[3]) : "r"(addr));
}
__device__ __forceinline__ void mma16816(float* c, const uint32_t* a,
                                         uint32_t b0, uint32_t b1) {
    asm("mma.sync.aligned.m16n8k16.row.col.f32.bf16.bf16.f32 "
        "{%0,%1,%2,%3}, {%4,%5,%6,%7}, {%8,%9}, {%0,%1,%2,%3};"
        : "+f"(c[0]), "+f"(c[1]), "+f"(c[2]), "+f"(c[3])
        : "r"(a[0]), "r"(a[1]), "r"(a[2]), "r"(a[3]), "r"(b0), "r"(b1));
}
#define FMA2(d, a, b) \
    asm("fma.rn.f32x2 %0, %1, %2, %0;" : "+l"(d) : "l"(a), "l"(b))
#define DUP2(d, s) \
    asm("mov.b64 %0, {%1, %1};" : "=l"(d) : "f"(s))
#define UNPK2(lo, hi, p) \
    asm("mov.b64 {%0, %1}, %2;" : "=f"(lo), "=f"(hi) : "l"(p))
__device__ __forceinline__ void cpasync16(uint32_t dst, const void* src) {
    asm volatile("cp.async.ca.shared.global [%0], [%1], 16;" :: "r"(dst), "l"(src));
}
#define CP_COMMIT() asm volatile("cp.async.commit_group;" ::: "memory")
#define CP_WAIT0()  asm volatile("cp.async.wait_group 0;" ::: "memory")

// ---------------- prep: W tables ----------------
// g_w3: per iter, bf16 h/l planes for k [i*64, i*64+48), expert rows padded to 112B
__global__ void prep_w3(const float* __restrict__ W) {
    int id = blockIdx.x * 256 + threadIdx.x;   // NIT*NE = 4096 threads
    if (id == 0) g_flag_count = 0;
    if (id >= NIT * NE) return;
    int i = id >> 6, e = id & 63;
    const float* src = W + (size_t)e * HDIM + i * KI;
    unsigned char* dh = g_w3 + (size_t)i * 14336 + e * 112;
    unsigned char* dl = dh + 7168;
#pragma unroll
    for (int kp = 0; kp < 24; ++kp) {          // 48 k = 24 pairs
        uint32_t h, l;
        splitpair(src[2 * kp], src[2 * kp + 1], h, l);
        *(uint32_t*)(dh + kp * 4) = h;
        *(uint32_t*)(dl + kp * 4) = l;
    }
}
// g_wf: per iter, fp32 [k][e] for k [i*64+48, i*64+64)
__global__ void prep_wf(const float* __restrict__ W) {
    int id = blockIdx.x * 256 + threadIdx.x;   // NIT*16*64 = 65536 threads
    if (id >= NIT * 16 * 64) return;
    int i = id >> 10, r = id & 1023;
    int k = r >> 6, e = r & 63;
    g_wf[id] = W[(size_t)e * HDIM + i * KI + KT + k];
}

// ---------------- main: hybrid tensor(3/4 K) + FFMA2(1/4 K) ----------------
__global__ void __launch_bounds__(NT, 2)
moe_gate_hybrid(const float* __restrict__ X, float* __restrict__ out) {
    extern __shared__ __align__(16) char smc[];
    const uint32_t sbase = s2u(smc);

    const int tid  = threadIdx.x;
    const int lane = tid & 31, wid = tid >> 5;     // 8 warps
    const int lrow = lane & 15, lkh = lane >> 4;
    const int tok0 = blockIdx.x * BM;
    const float* Xg = X + (size_t)tok0 * HDIM;

    // tensor ldmatrix lane addresses (pad-112 rows; kstep = +32B plain add)
    const uint32_t aH = sbase + XH_OFF + (uint32_t)((wid * 16 + lrow) * 112 + lkh * 16);
    const uint32_t aL = aH + (XL_OFF - XH_OFF);
    uint32_t bH[4];
#pragma unroll
    for (int np = 0; np < 4; ++np)
        bH[np] = sbase + W3_OFF + (uint32_t)((np * 16 + lrow) * 112 + lkh * 16);

    // fma thread tile: tokens t0..t0+3, expert pairs eg*8 + {0,2,4,6}
    const int eg = lane & 7;
    const int tg = (lane >> 3) & 3;
    const int t0 = wid * 16 + tg * 4;

    float accT[8][4];
    uint64_t accF[4][4];
#pragma unroll
    for (int nt = 0; nt < 8; ++nt)
#pragma unroll
        for (int q = 0; q < 4; ++q) accT[nt][q] = 0.0f;
#pragma unroll
    for (int p = 0; p < 4; ++p)
#pragma unroll
        for (int t = 0; t < 4; ++t) accF[p][t] = 0ull;

    float4 xa[6];   // tensor X staging: 128 tok x 48 k = 1536 float4 / 256 thr

#define LDG_XT(ii)                                                              \
    {                                                                           \
        _Pragma("unroll")                                                       \
        for (int it = 0; it < 6; ++it) {                                        \
            int f = it * NT + tid;                                              \
            int row = f / 12, q = f % 12;                                       \
            xa[it] = *(const float4*)(Xg + (size_t)row * HDIM + (ii) * KI + q * 4); \
        }                                                                       \
    }

#define CVT_XT(bufo)                                                            \
    {                                                                           \
        _Pragma("unroll")                                                       \
        for (int it = 0; it < 6; ++it) {                                        \
            int f = it * NT + tid;                                              \
            int row = f / 12, q = f % 12;                                       \
            uint32_t h0, l0, h1, l1;                                            \
            splitpair(xa[it].x, xa[it].y, h0, l0);                              \
            splitpair(xa[it].z, xa[it].w, h1, l1);                              \
            char* base = smc + (bufo) + row * 112 + q * 8;                      \
            *(uint2*)(base + XH_OFF) = make_uint2(h0, h1);                      \
            *(uint2*)(base + XL_OFF) = make_uint2(l0, l1);                      \
        }                                                                       \
    }

#define CP_ALL(ii, bufo)                                                        \
    {                                                                           \
        /* tensor W planes: linear 14336B copy (896 chunks) */                  \
        const char* ws = (const char*)g_w3 + (size_t)(ii) * 14336;              \
        _Pragma("unroll")                                                       \
        for (int q = 0; q < 4; ++q) {                                           \
            int idx = q * NT + tid;                                             \
            if (idx < 896)                                                      \
                cpasync16(sbase + (bufo) + W3_OFF + idx * 16, ws + idx * 16);   \
        }                                                                       \
        /* fma W: linear 4096B copy (256 chunks) */                             \
        const char* wf = (const char*)g_wf + (size_t)(ii) * 4096;               \
        cpasync16(sbase + (bufo) + WF_OFF + tid * 16, wf + tid * 16);           \
        /* fma X: 128 tok x 64B from global (512 chunks) */                     \
        _Pragma("unroll")                                                       \
        for (int q = 0; q < 2; ++q) {                                           \
            int idx = q * NT + tid;                                             \
            int t = idx >> 2, seg = idx & 3;                                    \
            cpasync16(sbase + (bufo) + XF_OFF + t * 80 + seg * 16,              \
                      (const char*)(Xg + (size_t)t * HDIM + (ii) * KI + KT) +   \
                          seg * 16);                                            \
        }                                                                       \
        CP_COMMIT();                                                            \
    }

    // ---- stage iteration 0 ----
    LDG_XT(0);
    CP_ALL(0, 0);
    CVT_XT(0);
    CP_WAIT0();
    __syncthreads();

    for (int i = 0; i < NIT; ++i) {
        const uint32_t bufR = (uint32_t)(i & 1) * BUFB;
        const uint32_t bufW = (uint32_t)((i + 1) & 1) * BUFB;
        const bool more = (i + 1 < NIT);

        if (more) {
            LDG_XT(i + 1);
            CP_ALL(i + 1, bufW);
        }

        // ---- tensor section: 3 ksteps x 4 np x 2 sub x 3 passes = 72 MMAs ----
#pragma unroll
        for (int ks = 0; ks < 3; ++ks) {
            const uint32_t ko = (uint32_t)(ks * 32);
            uint32_t Ah[4], Al[4];
            ldsm4(Ah, aH + bufR + ko);
            ldsm4(Al, aL + bufR + ko);
#pragma unroll
            for (int np = 0; np < 4; ++np) {
                uint32_t Bh[4], Bl[4];
                ldsm4(Bh, bH[np] + bufR + ko);
                ldsm4(Bl, bH[np] + bufR + ko + 7168);
#pragma unroll
                for (int sub = 0; sub < 2; ++sub) {
                    float* cc = accT[np * 2 + sub];
                    mma16816(cc, Ah, Bh[sub], Bh[2 + sub]);   // h*h
                    mma16816(cc, Ah, Bl[sub], Bl[2 + sub]);   // h*l
                    mma16816(cc, Al, Bh[sub], Bh[2 + sub]);   // l*h
                }
            }
        }

        // ---- fma section: 16 kk exact fp32 on the idle FMA pipe ----
        {
            const char* xf = smc + bufR + XF_OFF;
            const char* wf = smc + bufR + WF_OFF;
#pragma unroll 4
            for (int kk = 0; kk < KF; ++kk) {
                uint64_t xd[4];
#pragma unroll
                for (int t = 0; t < 4; ++t) {
                    float xv = *(const float*)(xf + (t0 + t) * 80 + kk * 4);
                    DUP2(xd[t], xv);
                }
                const char* wrow = wf + kk * 256 + eg * 32;
                ulonglong2 wA = *(const ulonglong2*)(wrow);       // pairs (0,1),(2,3)
                ulonglong2 wB = *(const ulonglong2*)(wrow + 16);  // pairs (4,5),(6,7)
#pragma unroll
                for (int t = 0; t < 4; ++t) {
                    FMA2(accF[0][t], xd[t], wA.x);
                    FMA2(accF[1][t], xd[t], wA.y);
                    FMA2(accF[2][t], xd[t], wB.x);
                    FMA2(accF[3][t], xd[t], wB.y);
                }
            }
        }

        if (more) {
            CVT_XT(bufW);
            CP_WAIT0();
        }
        __syncthreads();
    }

    // ---- merge: tensor fragments write lg, then fma accs add in ----
    float* lg = (float*)smc;
    const int g = lane >> 2, tig = lane & 3;
#pragma unroll
    for (int nt = 0; nt < 8; ++nt) {
        int r0 = wid * 16 + g;
        int e0 = nt * 8 + tig * 2;
        lg[r0 * 66 + e0]           = accT[nt][0];
        lg[r0 * 66 + e0 + 1]       = accT[nt][1];
        lg[(r0 + 8) * 66 + e0]     = accT[nt][2];
        lg[(r0 + 8) * 66 + e0 + 1] = accT[nt][3];
    }
    __syncthreads();
#pragma unroll
    for (int p = 0; p < 4; ++p) {
        int e = eg * 8 + 2 * p;
#pragma unroll
        for (int t = 0; t < 4; ++t) {
            float lo, hi;
            UNPK2(lo, hi, accF[p][t]);
            lg[(t0 + t) * 66 + e]     += lo;
            lg[(t0 + t) * 66 + e + 1] += hi;
        }
    }
    __syncthreads();

    // ---- per-token softmax + top-3 + near-tie flag (threads 0..127) ----
    if (tid < BM) {
        const int t = tid;
        const float* row = lg + t * 66;
        float mx = row[0];
#pragma unroll 8
        for (int e = 1; e < NE; ++e) mx = fmaxf(mx, row[e]);
        float sum = 0.0f;
        float s1 = -3.4e38f, s2 = -3.4e38f, s3 = -3.4e38f;
        int i1 = 0, i2 = 0;
#pragma unroll 8
        for (int e = 0; e < NE; ++e) {
            float l = row[e];
            sum += expf(l - mx);
            if (l > s1)      { s3 = s2; s2 = s1; i2 = i1; s1 = l; i1 = e; }
            else if (l > s2) { s3 = s2; s2 = l; i2 = e; }
            else if (l > s3) { s3 = l; }
        }
        float inv = 1.0f / sum;
        int gt = tok0 + t;
        out[2 * gt]               = (float)i1;
        out[2 * gt + 1]           = (float)i2;
        out[2 * TOK + 2 * gt]     = expf(s1 - mx) * inv;
        out[2 * TOK + 2 * gt + 1] = expf(s2 - mx) * inv;
        if ((s1 - s2 < TAU) || (s2 - s3 < TAU)) {
            int sl = atomicAdd(&g_flag_count, 1);
            if (sl < TOK) g_flag_list[sl] = gt;
        }
    }
}

// ---------------- cleanup: fp64 recompute of near-tie tokens (8-way ILP) ----------------
__global__ void cleanup_kernel(const float* __restrict__ X, const float* __restrict__ W,
                               float* __restrict__ out) {
    __shared__ double sred[128];
    __shared__ double lgs[64];
    int nf = g_flag_count;
    if (nf > TOK) nf = TOK;
    for (int i = blockIdx.x; i < nf; i += gridDim.x) {
        int t = g_flag_list[i];
        int e  = threadIdx.x & 63;
        int kh = threadIdx.x >> 6;
        const float4* xr = (const float4*)(X + (size_t)t * HDIM + kh * 2048);
        const float4* wr = (const float4*)(W + (size_t)e * HDIM + kh * 2048);
        double a0 = 0, a1 = 0, a2 = 0, a3 = 0, a4 = 0, a5 = 0, a6 = 0, a7 = 0;
#pragma unroll 4
        for (int q = 0; q < 512; q += 2) {
            float4 x0 = xr[q],     w0 = wr[q];
            float4 x1 = xr[q + 1], w1 = wr[q + 1];
            a0 += (double)x0.x * w0.x;  a1 += (double)x0.y * w0.y;
            a2 += (double)x0.z * w0.z;  a3 += (double)x0.w * w0.w;
            a4 += (double)x1.x * w1.x;  a5 += (double)x1.y * w1.y;
            a6 += (double)x1.z * w1.z;  a7 += (double)x1.w * w1.w;
        }
        sred[threadIdx.x] = ((a0 + a1) + (a2 + a3)) + ((a4 + a5) + (a6 + a7));
        __syncthreads();
        if (threadIdx.x < 64) lgs[threadIdx.x] = sred[threadIdx.x] + sred[threadIdx.x + 64];
        __syncthreads();
        if (threadIdx.x == 0) {
            double mx = lgs[0];
            for (int q = 1; q < NE; ++q) if (lgs[q] > mx) mx = lgs[q];
            double sum = 0.0;
            double s1 = -1e300, s2 = -1e300;
            int i1 = 0, i2 = 0;
            for (int q = 0; q < NE; ++q) {
                double l = lgs[q];
                sum += exp(l - mx);
                if (l > s1)      { s2 = s1; i2 = i1; s1 = l; i1 = q; }
                else if (l > s2) { s2 = l; i2 = q; }
            }
            double inv = 1.0 / sum;
            out[2 * t]               = (float)i1;
            out[2 * t + 1]           = (float)i2;
            out[2 * TOK + 2 * t]     = (float)(exp(s1 - mx) * inv);
            out[2 * TOK + 2 * t + 1] = (float)(exp(s2 - mx) * inv);
        }
        __syncthreads();
    }
}

// ---------------- launch ----------------
extern "C" void kernel_launch(void* const* d_in, const int* in_sizes, int n_in,
                              void* d_out, int out_size) {
    const float* X = (const float*)d_in[0];
    const float* W = (const float*)d_in[1];
    float* out = (float*)d_out;

    static bool once = []() {
        cudaFuncSetAttribute(moe_gate_hybrid, cudaFuncAttributeMaxDynamicSharedMemorySize,
                             SMEMB);
        return true;
    }();
    (void)once;

    prep_w3<<<16, 256>>>(W);
    prep_wf<<<256, 256>>>(W);
    moe_gate_hybrid<<<TOK / BM, NT, SMEMB>>>(X, out);
    cleanup_kernel<<<256, 128>>>(X, W, out);
}